// round 12
// baseline (speedup 1.0000x reference)
#include <cuda_runtime.h>
#include <cuda_bf16.h>

namespace {

typedef unsigned int  u32;
typedef unsigned long long u64;

constexpr int Bb  = 2;
constexpr int Nn  = 512;   // context nodes = GEMM K
constexpr int Mm  = 256;
constexpr int Dd  = 32;
constexpr int Tt  = 128;
constexpr int ORD = 2;
constexpr int CO  = 64;

constexpr int RR  = ORD * Mm;          // 512 GEMM rows per b: r = k*256+m
constexpr int NC  = (Dd + 1) * Tt;     // 4224 GEMM cols per b: c = d*128+t, d=32 -> denom plane

// ---------------- scratch (device globals; allocation-free) ----------------
__device__ __nv_bfloat16 d_Ah[Bb * RR * Nn];      // 1 MB
__device__ __nv_bfloat16 d_Al[Bb * RR * Nn];
__device__ __nv_bfloat16 d_Gh[(size_t)Bb * NC * Nn];  // 8.65 MB
__device__ __nv_bfloat16 d_Gl[(size_t)Bb * NC * Nn];
__device__ float         d_Cb[(size_t)Bb * RR * NC];  // 17.3 MB

__device__ __forceinline__ void bsplit(float v, __nv_bfloat16& h, __nv_bfloat16& l) {
    h = __float2bfloat16(v);
    l = __float2bfloat16(v - __bfloat162float(h));
}
__device__ __forceinline__ void ffma2(u64& d, u64 a, u64 b) {
    asm("fma.rn.f32x2 %0, %1, %2, %0;" : "+l"(d) : "l"(a), "l"(b));
}
__device__ __forceinline__ u64 dup2(float v) {
    u64 r; asm("mov.b64 %0, {%1, %1};" : "=l"(r) : "f"(v)); return r;
}
__device__ __forceinline__ float lo32(u64 v) { return __uint_as_float((u32)v); }
__device__ __forceinline__ float hi32(u64 v) { return __uint_as_float((u32)(v >> 32)); }

__device__ __forceinline__ void mma16816(float* c, const u32* a, const u32* b) {
    asm volatile(
        "mma.sync.aligned.m16n8k16.row.col.f32.bf16.bf16.f32 "
        "{%0,%1,%2,%3}, {%4,%5,%6,%7}, {%8,%9}, {%0,%1,%2,%3};\n"
        : "+f"(c[0]), "+f"(c[1]), "+f"(c[2]), "+f"(c[3])
        : "r"(a[0]), "r"(a[1]), "r"(a[2]), "r"(a[3]), "r"(b[0]), "r"(b[1]));
}

// ================= kernel A: split adj -> bf16 hi/lo =================
__global__ void __launch_bounds__(256)
k_split_adj(const float* __restrict__ adj) {
    int i4 = blockIdx.x * 256 + threadIdx.x;           // 131072 float4's
    float4 v = reinterpret_cast<const float4*>(adj)[i4];
    __nv_bfloat16 h0, l0, h1, l1, h2, l2, h3, l3;
    bsplit(v.x, h0, l0); bsplit(v.y, h1, l1);
    bsplit(v.z, h2, l2); bsplit(v.w, h3, l3);
    int o = i4 * 4;
    *reinterpret_cast<__nv_bfloat162*>(&d_Ah[o])     = __nv_bfloat162(h0, h1);
    *reinterpret_cast<__nv_bfloat162*>(&d_Ah[o + 2]) = __nv_bfloat162(h2, h3);
    *reinterpret_cast<__nv_bfloat162*>(&d_Al[o])     = __nv_bfloat162(l0, l1);
    *reinterpret_cast<__nv_bfloat162*>(&d_Al[o + 2]) = __nv_bfloat162(l2, l3);
}

// ================= kernel B: build G^T (hi/lo) =================
// G[c=(dd*128+t)][n] = z[t,n] * fc[b,n,dd,t]   (dd<32)
// G[4096+t][n]      = z[t,n]                    (denom plane)
struct SB {
    float ftile[64][132];   // [n'][t]
    float ztile[128][69];   // [t][n']
};
__global__ void __launch_bounds__(256)
k_build_G(const float* __restrict__ fc, const float* __restrict__ mask) {
    extern __shared__ char raw[];
    SB& S = *reinterpret_cast<SB*>(raw);
    const int dd = blockIdx.x;       // 0..32
    const int nb = blockIdx.y;       // 0..7  (64 n each)
    const int b  = blockIdx.z;
    const int tid = threadIdx.x;

    {   // z tile: rows t, 64 n
        int t = tid >> 1, h = tid & 1;
        const float4* mp = reinterpret_cast<const float4*>(
            &mask[(size_t)(b * Tt + t) * Nn + nb * 64 + h * 32]);
        #pragma unroll
        for (int i = 0; i < 8; ++i) {
            float4 v = mp[i];
            S.ztile[t][h * 32 + i * 4 + 0] = 1.0f - v.x;
            S.ztile[t][h * 32 + i * 4 + 1] = 1.0f - v.y;
            S.ztile[t][h * 32 + i * 4 + 2] = 1.0f - v.z;
            S.ztile[t][h * 32 + i * 4 + 3] = 1.0f - v.w;
        }
    }
    if (dd < Dd) {  // fc tile: rows n' (64), 128 t
        int r = tid >> 2, q = tid & 3;
        const float4* fp = reinterpret_cast<const float4*>(
            &fc[((size_t)(b * Nn + nb * 64 + r) * Dd + dd) * Tt + q * 32]);
        #pragma unroll
        for (int i = 0; i < 8; ++i) {
            float4 v = fp[i];
            S.ftile[r][q * 32 + i * 4 + 0] = v.x;
            S.ftile[r][q * 32 + i * 4 + 1] = v.y;
            S.ftile[r][q * 32 + i * 4 + 2] = v.z;
            S.ftile[r][q * 32 + i * 4 + 3] = v.w;
        }
    }
    __syncthreads();

    const int t = tid & 127, h = tid >> 7;
    const int c = (dd < Dd) ? dd * Tt + t : Dd * Tt + t;
    const size_t obase = ((size_t)b * NC + c) * Nn + nb * 64 + h * 32;
    #pragma unroll
    for (int j = 0; j < 32; j += 2) {
        int n0 = h * 32 + j;
        float z0 = S.ztile[t][n0], z1 = S.ztile[t][n0 + 1];
        float v0 = (dd < Dd ? S.ftile[n0][t]     : 1.0f) * z0;
        float v1 = (dd < Dd ? S.ftile[n0 + 1][t] : 1.0f) * z1;
        __nv_bfloat16 h0, l0, h1, l1;
        bsplit(v0, h0, l0); bsplit(v1, h1, l1);
        *reinterpret_cast<__nv_bfloat162*>(&d_Gh[obase + j]) = __nv_bfloat162(h0, h1);
        *reinterpret_cast<__nv_bfloat162*>(&d_Gl[obase + j]) = __nv_bfloat162(l0, l1);
    }
}

// ================= kernel C: HMMA GEMM =================
// C[b][r][c] = sum_n (Ah+Al)[r][n] * (Gh+Gl)[c][n]  (drop lo*lo)
constexpr int BKk = 64;
constexpr int LDK = 72;     // padded smem row (bf16): conflict-free frag loads
struct SC {
    __nv_bfloat16 Ah[128][LDK];
    __nv_bfloat16 Al[128][LDK];
    __nv_bfloat16 Bh[128][LDK];
    __nv_bfloat16 Bl[128][LDK];
};
__global__ void __launch_bounds__(256)
k_gemm(void) {
    extern __shared__ char raw[];
    SC& S = *reinterpret_cast<SC*>(raw);
    const int nt = blockIdx.x;   // 0..32
    const int mt = blockIdx.y;   // 0..3
    const int b  = blockIdx.z;
    const int tid = threadIdx.x;
    const int w   = tid >> 5;
    const int lane = tid & 31;
    const int g  = lane >> 2;
    const int tg = lane & 3;
    const int wm = w & 1;        // 2 M-warps (64 rows each)
    const int wn = w >> 1;       // 4 N-warps (32 cols each)

    float acc[4][4][4];
    #pragma unroll
    for (int i = 0; i < 4; ++i)
        #pragma unroll
        for (int j = 0; j < 4; ++j)
            #pragma unroll
            for (int q = 0; q < 4; ++q) acc[i][j][q] = 0.0f;

    const int r  = tid >> 1;     // loader row 0..127
    const int hh = tid & 1;
    const size_t aRow = (size_t)(b * RR + mt * 128 + r) * Nn;
    const size_t bRow = ((size_t)b * NC + nt * 128 + r) * Nn;

    for (int kc = 0; kc < Nn / BKk; ++kc) {
        const int kof = kc * BKk + hh * 32;
        {
            const uint4* sa = reinterpret_cast<const uint4*>(&d_Ah[aRow + kof]);
            const uint4* sl = reinterpret_cast<const uint4*>(&d_Al[aRow + kof]);
            const uint4* gb = reinterpret_cast<const uint4*>(&d_Gh[bRow + kof]);
            const uint4* gl = reinterpret_cast<const uint4*>(&d_Gl[bRow + kof]);
            #pragma unroll
            for (int q = 0; q < 4; ++q) {
                *reinterpret_cast<uint4*>(&S.Ah[r][hh * 32 + q * 8]) = sa[q];
                *reinterpret_cast<uint4*>(&S.Al[r][hh * 32 + q * 8]) = sl[q];
                *reinterpret_cast<uint4*>(&S.Bh[r][hh * 32 + q * 8]) = gb[q];
                *reinterpret_cast<uint4*>(&S.Bl[r][hh * 32 + q * 8]) = gl[q];
            }
        }
        __syncthreads();

        #pragma unroll
        for (int ks = 0; ks < BKk / 16; ++ks) {
            const int ck = ks * 16;
            u32 ah[4][4], bh[4][2], bl[4][2];
            #pragma unroll
            for (int i = 0; i < 4; ++i) {
                int m0 = wm * 64 + i * 16;
                ah[i][0] = *reinterpret_cast<const u32*>(&S.Ah[m0 + g    ][ck + 2 * tg]);
                ah[i][1] = *reinterpret_cast<const u32*>(&S.Ah[m0 + 8 + g][ck + 2 * tg]);
                ah[i][2] = *reinterpret_cast<const u32*>(&S.Ah[m0 + g    ][ck + 8 + 2 * tg]);
                ah[i][3] = *reinterpret_cast<const u32*>(&S.Ah[m0 + 8 + g][ck + 8 + 2 * tg]);
            }
            #pragma unroll
            for (int j = 0; j < 4; ++j) {
                int n0 = wn * 32 + j * 8 + g;
                bh[j][0] = *reinterpret_cast<const u32*>(&S.Bh[n0][ck + 2 * tg]);
                bh[j][1] = *reinterpret_cast<const u32*>(&S.Bh[n0][ck + 8 + 2 * tg]);
                bl[j][0] = *reinterpret_cast<const u32*>(&S.Bl[n0][ck + 2 * tg]);
                bl[j][1] = *reinterpret_cast<const u32*>(&S.Bl[n0][ck + 8 + 2 * tg]);
            }
            #pragma unroll
            for (int i = 0; i < 4; ++i)
                #pragma unroll
                for (int j = 0; j < 4; ++j) {
                    mma16816(acc[i][j], ah[i], bh[j]);   // hi*hi
                    mma16816(acc[i][j], ah[i], bl[j]);   // hi*lo
                }
            u32 al[4][4];
            #pragma unroll
            for (int i = 0; i < 4; ++i) {
                int m0 = wm * 64 + i * 16;
                al[i][0] = *reinterpret_cast<const u32*>(&S.Al[m0 + g    ][ck + 2 * tg]);
                al[i][1] = *reinterpret_cast<const u32*>(&S.Al[m0 + 8 + g][ck + 2 * tg]);
                al[i][2] = *reinterpret_cast<const u32*>(&S.Al[m0 + g    ][ck + 8 + 2 * tg]);
                al[i][3] = *reinterpret_cast<const u32*>(&S.Al[m0 + 8 + g][ck + 8 + 2 * tg]);
            }
            #pragma unroll
            for (int i = 0; i < 4; ++i)
                #pragma unroll
                for (int j = 0; j < 4; ++j)
                    mma16816(acc[i][j], al[i], bh[j]);   // lo*hi
        }
        __syncthreads();
    }

    // epilogue: write raw C
    #pragma unroll
    for (int i = 0; i < 4; ++i) {
        const int r0 = mt * 128 + wm * 64 + i * 16 + g;
        #pragma unroll
        for (int j = 0; j < 4; ++j) {
            const int col = nt * 128 + wn * 32 + j * 8 + 2 * tg;
            float* p0 = &d_Cb[((size_t)(b * RR) + r0) * NC + col];
            *reinterpret_cast<float2*>(p0)            = make_float2(acc[i][j][0], acc[i][j][1]);
            *reinterpret_cast<float2*>(p0 + 8 * NC)   = make_float2(acc[i][j][2], acc[i][j][3]);
        }
    }
}

// ================= kernel D: epilogue + MLP (t-pair FFMA2 packing) =================
struct SD {
    union {
        float agg[96][132];     // channels x t
        float ysm[64][133];     // outputs x t
    } u;
    float Wt[96][64];           // W transposed [c][o]: 24 KB
};
__global__ void __launch_bounds__(128)
k_epi(const float* __restrict__ ft, const float* __restrict__ Wm,
      const float* __restrict__ bm, float* __restrict__ out) {
    extern __shared__ char raw[];
    SD& S = *reinterpret_cast<SD*>(raw);
    const int m = blockIdx.x;
    const int b = blockIdx.y;
    const int tid = threadIdx.x;   // = t in step 1 / final store

    // W transposed, coalesced read + smem scatter
    for (int idx = tid; idx < CO * 96; idx += 128) {
        int o = idx / 96, c = idx % 96;
        S.Wt[c][o] = Wm[idx];
    }

    // step 1: assemble agg channels (thread = t, coalesced over Cb/ft)
    {
        const size_t r0 = (size_t)(b * RR + m) * NC;          // k=0 row
        const size_t r1 = (size_t)(b * RR + Mm + m) * NC;     // k=1 row
        const float iv0 = 1.0f / (d_Cb[r0 + Dd * Tt + tid] + 1.0f);
        const float iv1 = 1.0f / (d_Cb[r1 + Dd * Tt + tid] + 1.0f);
        const float* ftb = &ft[(size_t)((b * Mm + m) * Dd) * Tt + tid];
        #pragma unroll 8
        for (int d = 0; d < Dd; ++d) {
            float ftv = ftb[(size_t)d * Tt];
            S.u.agg[d][tid]          = ftv;
            S.u.agg[Dd + d][tid]     = fmaf(d_Cb[r0 + d * Tt + tid], iv0, ftv);
            S.u.agg[2 * Dd + d][tid] = fmaf(d_Cb[r1 + d * Tt + tid], iv1, ftv);
        }
    }
    __syncthreads();

    // step 2: MLP — lane = output channel, FFMA2 packed over t-pairs.
    // The (t,t+1) operand is a native contiguous u64 from smem; only the
    // weight needs dup2, ONCE per channel (not per t).
    const int w = tid >> 5, l = tid & 31;
    const int o  = (w & 1) * 32 + l;    // output channel
    const int th = (w >> 1) * 64;       // t-half: 64 t's = 32 pairs
    u64 acc[32];
    #pragma unroll
    for (int i = 0; i < 32; ++i) acc[i] = 0ull;

    for (int c = 0; c < 96; ++c) {
        const u64 wv = dup2(S.Wt[c][o]);
        const ulonglong2* ap = reinterpret_cast<const ulonglong2*>(&S.u.agg[c][th]);
        #pragma unroll
        for (int i = 0; i < 16; ++i) {
            ulonglong2 av = ap[i];      // broadcast LDS.128: 4 t's
            ffma2(acc[2 * i + 0], wv, av.x);
            ffma2(acc[2 * i + 1], wv, av.y);
        }
    }
    __syncthreads();   // agg reads done before ysm overwrites the union

    {
        const float bias = bm[o];
        #pragma unroll
        for (int i = 0; i < 32; ++i) {
            S.u.ysm[o][th + 2 * i]     = fmaxf(lo32(acc[i]) + bias, 0.0f);
            S.u.ysm[o][th + 2 * i + 1] = fmaxf(hi32(acc[i]) + bias, 0.0f);
        }
    }
    __syncthreads();

    // final: t-coalesced global store
    float* ob = &out[(size_t)((b * Mm + m) * CO) * Tt + tid];
    #pragma unroll 8
    for (int o2 = 0; o2 < CO; ++o2)
        ob[(size_t)o2 * Tt] = S.u.ysm[o2][tid];
}

} // namespace

extern "C" void kernel_launch(void* const* d_in, const int* in_sizes, int n_in,
                              void* d_out, int out_size) {
    const float* fc   = (const float*)d_in[0];  // [2,512,32,128]
    const float* ft   = (const float*)d_in[1];  // [2,256,32,128]
    const float* adj  = (const float*)d_in[2];  // [2,2,256,512]
    const float* mask = (const float*)d_in[3];  // [2,128,512]
    const float* Wm   = (const float*)d_in[4];  // [64,96]
    const float* bm   = (const float*)d_in[5];  // [64]
    float* out = (float*)d_out;                 // [2,256,64,128]

    static bool init = false;
    if (!init) {
        cudaFuncSetAttribute(k_build_G, cudaFuncAttributeMaxDynamicSharedMemorySize, (int)sizeof(SB));
        cudaFuncSetAttribute(k_gemm,    cudaFuncAttributeMaxDynamicSharedMemorySize, (int)sizeof(SC));
        cudaFuncSetAttribute(k_epi,     cudaFuncAttributeMaxDynamicSharedMemorySize, (int)sizeof(SD));
        init = true;
    }

    k_split_adj<<<512, 256>>>(adj);
    k_build_G<<<dim3(Dd + 1, 8, Bb), 256, sizeof(SB)>>>(fc, mask);
    k_gemm<<<dim3(NC / 128, RR / 128, Bb), 256, sizeof(SC)>>>();
    k_epi<<<dim3(Mm, Bb), 128, sizeof(SD)>>>(ft, Wm, bm, out);
}

// round 13
// speedup vs baseline: 1.0359x; 1.0359x over previous
#include <cuda_runtime.h>
#include <cuda_bf16.h>

namespace {

typedef unsigned int  u32;
typedef unsigned long long u64;

constexpr int Bb  = 2;
constexpr int Nn  = 512;   // context nodes = GEMM K
constexpr int Mm  = 256;
constexpr int Dd  = 32;
constexpr int Tt  = 128;
constexpr int ORD = 2;
constexpr int CO  = 64;

constexpr int RR  = ORD * Mm;          // 512 GEMM rows per b: r = k*256+m
constexpr int NC  = (Dd + 1) * Tt;     // 4224 GEMM cols per b: c = d*128+t, d=32 -> denom plane

// ---------------- scratch (device globals; allocation-free) ----------------
__device__ __nv_bfloat16 d_Ah[Bb * RR * Nn];      // 1 MB
__device__ __nv_bfloat16 d_Al[Bb * RR * Nn];
__device__ __nv_bfloat16 d_Gh[(size_t)Bb * NC * Nn];  // 8.65 MB
__device__ __nv_bfloat16 d_Gl[(size_t)Bb * NC * Nn];
__device__ float         d_Cb[(size_t)Bb * RR * NC];  // 17.3 MB

__device__ __forceinline__ void bsplit(float v, __nv_bfloat16& h, __nv_bfloat16& l) {
    h = __float2bfloat16(v);
    l = __float2bfloat16(v - __bfloat162float(h));
}
__device__ __forceinline__ void ffma2(u64& d, u64 a, u64 b) {
    asm("fma.rn.f32x2 %0, %1, %2, %0;" : "+l"(d) : "l"(a), "l"(b));
}
__device__ __forceinline__ u64 dup2(float v) {
    u64 r; asm("mov.b64 %0, {%1, %1};" : "=l"(r) : "f"(v)); return r;
}
__device__ __forceinline__ float lo32(u64 v) { return __uint_as_float((u32)v); }
__device__ __forceinline__ float hi32(u64 v) { return __uint_as_float((u32)(v >> 32)); }

__device__ __forceinline__ void mma16816(float* c, const u32* a, const u32* b) {
    asm volatile(
        "mma.sync.aligned.m16n8k16.row.col.f32.bf16.bf16.f32 "
        "{%0,%1,%2,%3}, {%4,%5,%6,%7}, {%8,%9}, {%0,%1,%2,%3};\n"
        : "+f"(c[0]), "+f"(c[1]), "+f"(c[2]), "+f"(c[3])
        : "r"(a[0]), "r"(a[1]), "r"(a[2]), "r"(a[3]), "r"(b[0]), "r"(b[1]));
}

// ================= kernel A: split adj -> bf16 hi/lo =================
__global__ void __launch_bounds__(256)
k_split_adj(const float* __restrict__ adj) {
    int i4 = blockIdx.x * 256 + threadIdx.x;           // 131072 float4's
    float4 v = reinterpret_cast<const float4*>(adj)[i4];
    __nv_bfloat16 h0, l0, h1, l1, h2, l2, h3, l3;
    bsplit(v.x, h0, l0); bsplit(v.y, h1, l1);
    bsplit(v.z, h2, l2); bsplit(v.w, h3, l3);
    int o = i4 * 4;
    *reinterpret_cast<__nv_bfloat162*>(&d_Ah[o])     = __nv_bfloat162(h0, h1);
    *reinterpret_cast<__nv_bfloat162*>(&d_Ah[o + 2]) = __nv_bfloat162(h2, h3);
    *reinterpret_cast<__nv_bfloat162*>(&d_Al[o])     = __nv_bfloat162(l0, l1);
    *reinterpret_cast<__nv_bfloat162*>(&d_Al[o + 2]) = __nv_bfloat162(l2, l3);
}

// ================= kernel B: build G^T (hi/lo) =================
// G[c=(dd*128+t)][n] = z[t,n] * fc[b,n,dd,t]   (dd<32)
// G[4096+t][n]      = z[t,n]                    (denom plane)
struct SB {
    float ftile[64][132];   // [n'][t]
    float ztile[128][69];   // [t][n']
};
__global__ void __launch_bounds__(256)
k_build_G(const float* __restrict__ fc, const float* __restrict__ mask) {
    extern __shared__ char raw[];
    SB& S = *reinterpret_cast<SB*>(raw);
    const int dd = blockIdx.x;       // 0..32
    const int nb = blockIdx.y;       // 0..7  (64 n each)
    const int b  = blockIdx.z;
    const int tid = threadIdx.x;

    {   // z tile: rows t, 64 n
        int t = tid >> 1, h = tid & 1;
        const float4* mp = reinterpret_cast<const float4*>(
            &mask[(size_t)(b * Tt + t) * Nn + nb * 64 + h * 32]);
        #pragma unroll
        for (int i = 0; i < 8; ++i) {
            float4 v = mp[i];
            S.ztile[t][h * 32 + i * 4 + 0] = 1.0f - v.x;
            S.ztile[t][h * 32 + i * 4 + 1] = 1.0f - v.y;
            S.ztile[t][h * 32 + i * 4 + 2] = 1.0f - v.z;
            S.ztile[t][h * 32 + i * 4 + 3] = 1.0f - v.w;
        }
    }
    if (dd < Dd) {  // fc tile: rows n' (64), 128 t
        int r = tid >> 2, q = tid & 3;
        const float4* fp = reinterpret_cast<const float4*>(
            &fc[((size_t)(b * Nn + nb * 64 + r) * Dd + dd) * Tt + q * 32]);
        #pragma unroll
        for (int i = 0; i < 8; ++i) {
            float4 v = fp[i];
            S.ftile[r][q * 32 + i * 4 + 0] = v.x;
            S.ftile[r][q * 32 + i * 4 + 1] = v.y;
            S.ftile[r][q * 32 + i * 4 + 2] = v.z;
            S.ftile[r][q * 32 + i * 4 + 3] = v.w;
        }
    }
    __syncthreads();

    const int t = tid & 127, h = tid >> 7;
    const int c = (dd < Dd) ? dd * Tt + t : Dd * Tt + t;
    const size_t obase = ((size_t)b * NC + c) * Nn + nb * 64 + h * 32;
    #pragma unroll
    for (int j = 0; j < 32; j += 2) {
        int n0 = h * 32 + j;
        float z0 = S.ztile[t][n0], z1 = S.ztile[t][n0 + 1];
        float v0 = (dd < Dd ? S.ftile[n0][t]     : 1.0f) * z0;
        float v1 = (dd < Dd ? S.ftile[n0 + 1][t] : 1.0f) * z1;
        __nv_bfloat16 h0, l0, h1, l1;
        bsplit(v0, h0, l0); bsplit(v1, h1, l1);
        *reinterpret_cast<__nv_bfloat162*>(&d_Gh[obase + j]) = __nv_bfloat162(h0, h1);
        *reinterpret_cast<__nv_bfloat162*>(&d_Gl[obase + j]) = __nv_bfloat162(l0, l1);
    }
}

// ================= kernel C: HMMA GEMM =================
// C[b][r][c] = sum_n (Ah+Al)[r][n] * (Gh+Gl)[c][n]  (drop lo*lo)
constexpr int BKk = 64;
constexpr int LDK = 72;     // padded smem row (bf16): conflict-free frag loads
struct SC {
    __nv_bfloat16 Ah[128][LDK];
    __nv_bfloat16 Al[128][LDK];
    __nv_bfloat16 Bh[128][LDK];
    __nv_bfloat16 Bl[128][LDK];
};
__global__ void __launch_bounds__(256)
k_gemm(void) {
    extern __shared__ char raw[];
    SC& S = *reinterpret_cast<SC*>(raw);
    const int nt = blockIdx.x;   // 0..32
    const int mt = blockIdx.y;   // 0..3
    const int b  = blockIdx.z;
    const int tid = threadIdx.x;
    const int w   = tid >> 5;
    const int lane = tid & 31;
    const int g  = lane >> 2;
    const int tg = lane & 3;
    const int wm = w & 1;        // 2 M-warps (64 rows each)
    const int wn = w >> 1;       // 4 N-warps (32 cols each)

    float acc[4][4][4];
    #pragma unroll
    for (int i = 0; i < 4; ++i)
        #pragma unroll
        for (int j = 0; j < 4; ++j)
            #pragma unroll
            for (int q = 0; q < 4; ++q) acc[i][j][q] = 0.0f;

    const int r  = tid >> 1;     // loader row 0..127
    const int hh = tid & 1;
    const size_t aRow = (size_t)(b * RR + mt * 128 + r) * Nn;
    const size_t bRow = ((size_t)b * NC + nt * 128 + r) * Nn;

    for (int kc = 0; kc < Nn / BKk; ++kc) {
        const int kof = kc * BKk + hh * 32;
        {
            const uint4* sa = reinterpret_cast<const uint4*>(&d_Ah[aRow + kof]);
            const uint4* sl = reinterpret_cast<const uint4*>(&d_Al[aRow + kof]);
            const uint4* gb = reinterpret_cast<const uint4*>(&d_Gh[bRow + kof]);
            const uint4* gl = reinterpret_cast<const uint4*>(&d_Gl[bRow + kof]);
            #pragma unroll
            for (int q = 0; q < 4; ++q) {
                *reinterpret_cast<uint4*>(&S.Ah[r][hh * 32 + q * 8]) = sa[q];
                *reinterpret_cast<uint4*>(&S.Al[r][hh * 32 + q * 8]) = sl[q];
                *reinterpret_cast<uint4*>(&S.Bh[r][hh * 32 + q * 8]) = gb[q];
                *reinterpret_cast<uint4*>(&S.Bl[r][hh * 32 + q * 8]) = gl[q];
            }
        }
        __syncthreads();

        #pragma unroll
        for (int ks = 0; ks < BKk / 16; ++ks) {
            const int ck = ks * 16;
            u32 ah[4][4], bh[4][2], bl[4][2];
            #pragma unroll
            for (int i = 0; i < 4; ++i) {
                int m0 = wm * 64 + i * 16;
                ah[i][0] = *reinterpret_cast<const u32*>(&S.Ah[m0 + g    ][ck + 2 * tg]);
                ah[i][1] = *reinterpret_cast<const u32*>(&S.Ah[m0 + 8 + g][ck + 2 * tg]);
                ah[i][2] = *reinterpret_cast<const u32*>(&S.Ah[m0 + g    ][ck + 8 + 2 * tg]);
                ah[i][3] = *reinterpret_cast<const u32*>(&S.Ah[m0 + 8 + g][ck + 8 + 2 * tg]);
            }
            #pragma unroll
            for (int j = 0; j < 4; ++j) {
                int n0 = wn * 32 + j * 8 + g;
                bh[j][0] = *reinterpret_cast<const u32*>(&S.Bh[n0][ck + 2 * tg]);
                bh[j][1] = *reinterpret_cast<const u32*>(&S.Bh[n0][ck + 8 + 2 * tg]);
                bl[j][0] = *reinterpret_cast<const u32*>(&S.Bl[n0][ck + 2 * tg]);
                bl[j][1] = *reinterpret_cast<const u32*>(&S.Bl[n0][ck + 8 + 2 * tg]);
            }
            #pragma unroll
            for (int i = 0; i < 4; ++i)
                #pragma unroll
                for (int j = 0; j < 4; ++j) {
                    mma16816(acc[i][j], ah[i], bh[j]);   // hi*hi
                    mma16816(acc[i][j], ah[i], bl[j]);   // hi*lo
                }
            u32 al[4][4];
            #pragma unroll
            for (int i = 0; i < 4; ++i) {
                int m0 = wm * 64 + i * 16;
                al[i][0] = *reinterpret_cast<const u32*>(&S.Al[m0 + g    ][ck + 2 * tg]);
                al[i][1] = *reinterpret_cast<const u32*>(&S.Al[m0 + 8 + g][ck + 2 * tg]);
                al[i][2] = *reinterpret_cast<const u32*>(&S.Al[m0 + g    ][ck + 8 + 2 * tg]);
                al[i][3] = *reinterpret_cast<const u32*>(&S.Al[m0 + 8 + g][ck + 8 + 2 * tg]);
            }
            #pragma unroll
            for (int i = 0; i < 4; ++i)
                #pragma unroll
                for (int j = 0; j < 4; ++j)
                    mma16816(acc[i][j], al[i], bh[j]);   // lo*hi
        }
        __syncthreads();
    }

    // epilogue: write raw C
    #pragma unroll
    for (int i = 0; i < 4; ++i) {
        const int r0 = mt * 128 + wm * 64 + i * 16 + g;
        #pragma unroll
        for (int j = 0; j < 4; ++j) {
            const int col = nt * 128 + wn * 32 + j * 8 + 2 * tg;
            float* p0 = &d_Cb[((size_t)(b * RR) + r0) * NC + col];
            *reinterpret_cast<float2*>(p0)            = make_float2(acc[i][j][0], acc[i][j][1]);
            *reinterpret_cast<float2*>(p0 + 8 * NC)   = make_float2(acc[i][j][2], acc[i][j][3]);
        }
    }
}

// ================= kernel D: epilogue + MLP (t-pair FFMA2, 256 threads) =================
struct SD {
    union {
        float agg[96][132];     // channels x t: 50.7 KB
        float ysm[64][133];     // outputs x t
    } u;
    float Wt[96][64];           // W transposed [c][o]: 24 KB
};
__global__ void __launch_bounds__(256)
k_epi(const float* __restrict__ ft, const float* __restrict__ Wm,
      const float* __restrict__ bm, float* __restrict__ out) {
    extern __shared__ char raw[];
    SD& S = *reinterpret_cast<SD*>(raw);
    const int m = blockIdx.x;
    const int b = blockIdx.y;
    const int tid = threadIdx.x;

    // W transposed, coalesced read + conflict-free smem scatter
    for (int idx = tid; idx < CO * 96; idx += 256) {
        int o = idx / 96, c = idx % 96;
        S.Wt[c][o] = Wm[idx];
    }

    // step 1: assemble agg channels. thread = (t = tid&127, d-half = tid>>7)
    {
        const int t    = tid & 127;
        const int half = tid >> 7;              // 16 d's each
        const size_t r0 = (size_t)(b * RR + m) * NC;          // k=0 row
        const size_t r1 = (size_t)(b * RR + Mm + m) * NC;     // k=1 row
        const float iv0 = 1.0f / (d_Cb[r0 + Dd * Tt + t] + 1.0f);
        const float iv1 = 1.0f / (d_Cb[r1 + Dd * Tt + t] + 1.0f);
        const float* ftb = &ft[(size_t)((b * Mm + m) * Dd) * Tt + t];
        #pragma unroll 8
        for (int dd = 0; dd < Dd / 2; ++dd) {
            int d = half * (Dd / 2) + dd;
            float ftv = ftb[(size_t)d * Tt];
            S.u.agg[d][t]          = ftv;
            S.u.agg[Dd + d][t]     = fmaf(d_Cb[r0 + d * Tt + t], iv0, ftv);
            S.u.agg[2 * Dd + d][t] = fmaf(d_Cb[r1 + d * Tt + t], iv1, ftv);
        }
    }
    __syncthreads();

    // step 2: MLP. thread = (o = tid&63, t-quarter q = tid>>6 -> 32 t = 16 pairs)
    // acc[16] u64 = 32 regs only; 8 broadcast LDS.128 per channel.
    const int o = tid & 63;
    const int q = tid >> 6;
    const int tb = q * 32;
    u64 acc[16];
    #pragma unroll
    for (int i = 0; i < 16; ++i) acc[i] = 0ull;

    for (int c = 0; c < 96; ++c) {
        const u64 wv = dup2(S.Wt[c][o]);       // one dup per channel
        const ulonglong2* ap = reinterpret_cast<const ulonglong2*>(&S.u.agg[c][tb]);
        #pragma unroll
        for (int i = 0; i < 8; ++i) {
            ulonglong2 av = ap[i];             // broadcast LDS.128 (4 t's)
            ffma2(acc[2 * i + 0], wv, av.x);
            ffma2(acc[2 * i + 1], wv, av.y);
        }
    }
    __syncthreads();   // agg reads done before ysm overwrites the union

    {
        const float bias = bm[o];
        #pragma unroll
        for (int i = 0; i < 16; ++i) {
            S.u.ysm[o][tb + 2 * i]     = fmaxf(lo32(acc[i]) + bias, 0.0f);
            S.u.ysm[o][tb + 2 * i + 1] = fmaxf(hi32(acc[i]) + bias, 0.0f);
        }
    }
    __syncthreads();

    // final: t-coalesced global store. thread = (t, o-half)
    {
        const int t    = tid & 127;
        const int half = tid >> 7;
        float* ob = &out[(size_t)((b * Mm + m) * CO) * Tt + t];
        #pragma unroll 8
        for (int i = 0; i < CO / 2; ++i) {
            int o2 = half * (CO / 2) + i;
            ob[(size_t)o2 * Tt] = S.u.ysm[o2][t];
        }
    }
}

} // namespace

extern "C" void kernel_launch(void* const* d_in, const int* in_sizes, int n_in,
                              void* d_out, int out_size) {
    const float* fc   = (const float*)d_in[0];  // [2,512,32,128]
    const float* ft   = (const float*)d_in[1];  // [2,256,32,128]
    const float* adj  = (const float*)d_in[2];  // [2,2,256,512]
    const float* mask = (const float*)d_in[3];  // [2,128,512]
    const float* Wm   = (const float*)d_in[4];  // [64,96]
    const float* bm   = (const float*)d_in[5];  // [64]
    float* out = (float*)d_out;                 // [2,256,64,128]

    static bool init = false;
    if (!init) {
        cudaFuncSetAttribute(k_build_G, cudaFuncAttributeMaxDynamicSharedMemorySize, (int)sizeof(SB));
        cudaFuncSetAttribute(k_gemm,    cudaFuncAttributeMaxDynamicSharedMemorySize, (int)sizeof(SC));
        cudaFuncSetAttribute(k_epi,     cudaFuncAttributeMaxDynamicSharedMemorySize, (int)sizeof(SD));
        init = true;
    }

    k_split_adj<<<512, 256>>>(adj);
    k_build_G<<<dim3(Dd + 1, 8, Bb), 256, sizeof(SB)>>>(fc, mask);
    k_gemm<<<dim3(NC / 128, RR / 128, Bb), 256, sizeof(SC)>>>();
    k_epi<<<dim3(Mm, Bb), 256, sizeof(SD)>>>(ft, Wm, bm, out);
}

// round 15
// speedup vs baseline: 1.2849x; 1.2404x over previous
#include <cuda_runtime.h>
#include <cuda_bf16.h>

namespace {

typedef unsigned int  u32;
typedef unsigned long long u64;

constexpr int Bb  = 2;
constexpr int Nn  = 512;   // context nodes = GEMM K
constexpr int Mm  = 256;
constexpr int Dd  = 32;
constexpr int Tt  = 128;
constexpr int ORD = 2;
constexpr int CO  = 64;

constexpr int RR  = ORD * Mm;          // 512 GEMM rows per b: r = k*256+m
constexpr int NC  = (Dd + 1) * Tt;     // 4224 GEMM cols per b: c = d*128+t, d=32 -> denom plane

// ---------------- scratch (device globals; allocation-free) ----------------
__device__ __nv_bfloat16 d_Ah[Bb * RR * Nn];      // 1 MB
__device__ __nv_bfloat16 d_Al[Bb * RR * Nn];
__device__ __nv_bfloat16 d_Gh[(size_t)Bb * NC * Nn];  // 8.65 MB
__device__ __nv_bfloat16 d_Gl[(size_t)Bb * NC * Nn];
__device__ float         d_Cb[(size_t)Bb * RR * NC];  // 17.3 MB

__device__ __forceinline__ void bsplit(float v, __nv_bfloat16& h, __nv_bfloat16& l) {
    h = __float2bfloat16(v);
    l = __float2bfloat16(v - __bfloat162float(h));
}
__device__ __forceinline__ void mma16816(float* c, const u32* a, const u32* b) {
    asm volatile(
        "mma.sync.aligned.m16n8k16.row.col.f32.bf16.bf16.f32 "
        "{%0,%1,%2,%3}, {%4,%5,%6,%7}, {%8,%9}, {%0,%1,%2,%3};\n"
        : "+f"(c[0]), "+f"(c[1]), "+f"(c[2]), "+f"(c[3])
        : "r"(a[0]), "r"(a[1]), "r"(a[2]), "r"(a[3]), "r"(b[0]), "r"(b[1]));
}

// ================= kernel A: split adj -> bf16 hi/lo =================
__global__ void __launch_bounds__(256)
k_split_adj(const float* __restrict__ adj) {
    int i4 = blockIdx.x * 256 + threadIdx.x;           // 131072 float4's
    float4 v = reinterpret_cast<const float4*>(adj)[i4];
    __nv_bfloat16 h0, l0, h1, l1, h2, l2, h3, l3;
    bsplit(v.x, h0, l0); bsplit(v.y, h1, l1);
    bsplit(v.z, h2, l2); bsplit(v.w, h3, l3);
    int o = i4 * 4;
    *reinterpret_cast<__nv_bfloat162*>(&d_Ah[o])     = __nv_bfloat162(h0, h1);
    *reinterpret_cast<__nv_bfloat162*>(&d_Ah[o + 2]) = __nv_bfloat162(h2, h3);
    *reinterpret_cast<__nv_bfloat162*>(&d_Al[o])     = __nv_bfloat162(l0, l1);
    *reinterpret_cast<__nv_bfloat162*>(&d_Al[o + 2]) = __nv_bfloat162(l2, l3);
}

// ================= kernel B: build G^T (hi/lo) =================
struct SB {
    float ftile[64][132];   // [n'][t]
    float ztile[128][69];   // [t][n']
};
__global__ void __launch_bounds__(256)
k_build_G(const float* __restrict__ fc, const float* __restrict__ mask) {
    extern __shared__ char raw[];
    SB& S = *reinterpret_cast<SB*>(raw);
    const int dd = blockIdx.x;       // 0..32
    const int nb = blockIdx.y;       // 0..7  (64 n each)
    const int b  = blockIdx.z;
    const int tid = threadIdx.x;

    {   // z tile: rows t, 64 n
        int t = tid >> 1, h = tid & 1;
        const float4* mp = reinterpret_cast<const float4*>(
            &mask[(size_t)(b * Tt + t) * Nn + nb * 64 + h * 32]);
        #pragma unroll
        for (int i = 0; i < 8; ++i) {
            float4 v = mp[i];
            S.ztile[t][h * 32 + i * 4 + 0] = 1.0f - v.x;
            S.ztile[t][h * 32 + i * 4 + 1] = 1.0f - v.y;
            S.ztile[t][h * 32 + i * 4 + 2] = 1.0f - v.z;
            S.ztile[t][h * 32 + i * 4 + 3] = 1.0f - v.w;
        }
    }
    if (dd < Dd) {  // fc tile: rows n' (64), 128 t
        int r = tid >> 2, q = tid & 3;
        const float4* fp = reinterpret_cast<const float4*>(
            &fc[((size_t)(b * Nn + nb * 64 + r) * Dd + dd) * Tt + q * 32]);
        #pragma unroll
        for (int i = 0; i < 8; ++i) {
            float4 v = fp[i];
            S.ftile[r][q * 32 + i * 4 + 0] = v.x;
            S.ftile[r][q * 32 + i * 4 + 1] = v.y;
            S.ftile[r][q * 32 + i * 4 + 2] = v.z;
            S.ftile[r][q * 32 + i * 4 + 3] = v.w;
        }
    }
    __syncthreads();

    const int t = tid & 127, h = tid >> 7;
    const int c = (dd < Dd) ? dd * Tt + t : Dd * Tt + t;
    const size_t obase = ((size_t)b * NC + c) * Nn + nb * 64 + h * 32;
    #pragma unroll
    for (int j = 0; j < 32; j += 2) {
        int n0 = h * 32 + j;
        float z0 = S.ztile[t][n0], z1 = S.ztile[t][n0 + 1];
        float v0 = (dd < Dd ? S.ftile[n0][t]     : 1.0f) * z0;
        float v1 = (dd < Dd ? S.ftile[n0 + 1][t] : 1.0f) * z1;
        __nv_bfloat16 h0, l0, h1, l1;
        bsplit(v0, h0, l0); bsplit(v1, h1, l1);
        *reinterpret_cast<__nv_bfloat162*>(&d_Gh[obase + j]) = __nv_bfloat162(h0, h1);
        *reinterpret_cast<__nv_bfloat162*>(&d_Gl[obase + j]) = __nv_bfloat162(l0, l1);
    }
}

// ================= kernel C: HMMA GEMM =================
constexpr int BKk = 64;
constexpr int LDK = 72;     // padded smem row (bf16): conflict-free frag loads
struct SC {
    __nv_bfloat16 Ah[128][LDK];
    __nv_bfloat16 Al[128][LDK];
    __nv_bfloat16 Bh[128][LDK];
    __nv_bfloat16 Bl[128][LDK];
};
__global__ void __launch_bounds__(256)
k_gemm(void) {
    extern __shared__ char raw[];
    SC& S = *reinterpret_cast<SC*>(raw);
    const int nt = blockIdx.x;   // 0..32
    const int mt = blockIdx.y;   // 0..3
    const int b  = blockIdx.z;
    const int tid = threadIdx.x;
    const int w   = tid >> 5;
    const int lane = tid & 31;
    const int g  = lane >> 2;
    const int tg = lane & 3;
    const int wm = w & 1;        // 2 M-warps (64 rows each)
    const int wn = w >> 1;       // 4 N-warps (32 cols each)

    float acc[4][4][4];
    #pragma unroll
    for (int i = 0; i < 4; ++i)
        #pragma unroll
        for (int j = 0; j < 4; ++j)
            #pragma unroll
            for (int q = 0; q < 4; ++q) acc[i][j][q] = 0.0f;

    const int r  = tid >> 1;     // loader row 0..127
    const int hh = tid & 1;
    const size_t aRow = (size_t)(b * RR + mt * 128 + r) * Nn;
    const size_t bRow = ((size_t)b * NC + nt * 128 + r) * Nn;

    for (int kc = 0; kc < Nn / BKk; ++kc) {
        const int kof = kc * BKk + hh * 32;
        {
            const uint4* sa = reinterpret_cast<const uint4*>(&d_Ah[aRow + kof]);
            const uint4* sl = reinterpret_cast<const uint4*>(&d_Al[aRow + kof]);
            const uint4* gb = reinterpret_cast<const uint4*>(&d_Gh[bRow + kof]);
            const uint4* gl = reinterpret_cast<const uint4*>(&d_Gl[bRow + kof]);
            #pragma unroll
            for (int q = 0; q < 4; ++q) {
                *reinterpret_cast<uint4*>(&S.Ah[r][hh * 32 + q * 8]) = sa[q];
                *reinterpret_cast<uint4*>(&S.Al[r][hh * 32 + q * 8]) = sl[q];
                *reinterpret_cast<uint4*>(&S.Bh[r][hh * 32 + q * 8]) = gb[q];
                *reinterpret_cast<uint4*>(&S.Bl[r][hh * 32 + q * 8]) = gl[q];
            }
        }
        __syncthreads();

        #pragma unroll
        for (int ks = 0; ks < BKk / 16; ++ks) {
            const int ck = ks * 16;
            u32 ah[4][4], bh[4][2], bl[4][2];
            #pragma unroll
            for (int i = 0; i < 4; ++i) {
                int m0 = wm * 64 + i * 16;
                ah[i][0] = *reinterpret_cast<const u32*>(&S.Ah[m0 + g    ][ck + 2 * tg]);
                ah[i][1] = *reinterpret_cast<const u32*>(&S.Ah[m0 + 8 + g][ck + 2 * tg]);
                ah[i][2] = *reinterpret_cast<const u32*>(&S.Ah[m0 + g    ][ck + 8 + 2 * tg]);
                ah[i][3] = *reinterpret_cast<const u32*>(&S.Ah[m0 + 8 + g][ck + 8 + 2 * tg]);
            }
            #pragma unroll
            for (int j = 0; j < 4; ++j) {
                int n0 = wn * 32 + j * 8 + g;
                bh[j][0] = *reinterpret_cast<const u32*>(&S.Bh[n0][ck + 2 * tg]);
                bh[j][1] = *reinterpret_cast<const u32*>(&S.Bh[n0][ck + 8 + 2 * tg]);
                bl[j][0] = *reinterpret_cast<const u32*>(&S.Bl[n0][ck + 2 * tg]);
                bl[j][1] = *reinterpret_cast<const u32*>(&S.Bl[n0][ck + 8 + 2 * tg]);
            }
            #pragma unroll
            for (int i = 0; i < 4; ++i)
                #pragma unroll
                for (int j = 0; j < 4; ++j) {
                    mma16816(acc[i][j], ah[i], bh[j]);   // hi*hi
                    mma16816(acc[i][j], ah[i], bl[j]);   // hi*lo
                }
            u32 al[4][4];
            #pragma unroll
            for (int i = 0; i < 4; ++i) {
                int m0 = wm * 64 + i * 16;
                al[i][0] = *reinterpret_cast<const u32*>(&S.Al[m0 + g    ][ck + 2 * tg]);
                al[i][1] = *reinterpret_cast<const u32*>(&S.Al[m0 + 8 + g][ck + 2 * tg]);
                al[i][2] = *reinterpret_cast<const u32*>(&S.Al[m0 + g    ][ck + 8 + 2 * tg]);
                al[i][3] = *reinterpret_cast<const u32*>(&S.Al[m0 + 8 + g][ck + 8 + 2 * tg]);
            }
            #pragma unroll
            for (int i = 0; i < 4; ++i)
                #pragma unroll
                for (int j = 0; j < 4; ++j)
                    mma16816(acc[i][j], al[i], bh[j]);   // lo*hi
        }
        __syncthreads();
    }

    // epilogue: write raw C
    #pragma unroll
    for (int i = 0; i < 4; ++i) {
        const int r0 = mt * 128 + wm * 64 + i * 16 + g;
        #pragma unroll
        for (int j = 0; j < 4; ++j) {
            const int col = nt * 128 + wn * 32 + j * 8 + 2 * tg;
            float* p0 = &d_Cb[((size_t)(b * RR) + r0) * NC + col];
            *reinterpret_cast<float2*>(p0)            = make_float2(acc[i][j][0], acc[i][j][1]);
            *reinterpret_cast<float2*>(p0 + 8 * NC)   = make_float2(acc[i][j][2], acc[i][j][3]);
        }
    }
}

// ================= kernel D: epilogue + MLP on tensor cores =================
// Per (b,m): Y[t=128, o=64] = aggT[t, c=96] @ W[o, c]  (bf16 hi/lo, drop lo*lo)
constexpr int LDC = 104;    // aggT/W row stride in bf16 (96 + 8 pad)
struct SD {
    union {
        struct {
            __nv_bfloat16 aggTh[128][LDC];   // 26.6 KB
            __nv_bfloat16 aggTl[128][LDC];   // 26.6 KB
        } a;
        float ysm[64][132];                  // 33.8 KB (reused after mma)
    } u;
    __nv_bfloat16 Wh[64][LDC];               // 13.3 KB
    __nv_bfloat16 Wl[64][LDC];               // 13.3 KB
};
__global__ void __launch_bounds__(256)
k_epi(const float* __restrict__ ft, const float* __restrict__ Wm,
      const float* __restrict__ bm, float* __restrict__ out) {
    extern __shared__ char raw[];
    SD& S = *reinterpret_cast<SD*>(raw);
    const int m = blockIdx.x;
    const int b = blockIdx.y;
    const int tid = threadIdx.x;

    // W -> bf16 hi/lo [o][c]
    for (int idx = tid; idx < CO * 96; idx += 256) {
        int o = idx / 96, c = idx % 96;
        __nv_bfloat16 h, l;
        bsplit(Wm[idx], h, l);
        S.Wh[o][c] = h;
        S.Wl[o][c] = l;
    }

    // step 1: assemble agg, transposed, bf16 hi/lo. thread = (t, d-half)
    {
        const int t    = tid & 127;
        const int half = tid >> 7;              // 16 d's each
        const size_t r0 = (size_t)(b * RR + m) * NC;          // k=0 row
        const size_t r1 = (size_t)(b * RR + Mm + m) * NC;     // k=1 row
        const float iv0 = 1.0f / (d_Cb[r0 + Dd * Tt + t] + 1.0f);
        const float iv1 = 1.0f / (d_Cb[r1 + Dd * Tt + t] + 1.0f);
        const float* ftb = &ft[(size_t)((b * Mm + m) * Dd) * Tt + t];
        #pragma unroll 4
        for (int dd = 0; dd < 16; dd += 2) {
            const int d0 = half * 16 + dd;
            const float f0 = ftb[(size_t)d0 * Tt];
            const float f1 = ftb[(size_t)(d0 + 1) * Tt];
            const float a0 = fmaf(d_Cb[r0 + d0 * Tt + t],       iv0, f0);
            const float a1 = fmaf(d_Cb[r0 + (d0 + 1) * Tt + t], iv0, f1);
            const float b0 = fmaf(d_Cb[r1 + d0 * Tt + t],       iv1, f0);
            const float b1 = fmaf(d_Cb[r1 + (d0 + 1) * Tt + t], iv1, f1);
            __nv_bfloat16 h0, l0, h1, l1;
            bsplit(f0, h0, l0); bsplit(f1, h1, l1);
            *reinterpret_cast<__nv_bfloat162*>(&S.u.a.aggTh[t][d0]) = __nv_bfloat162(h0, h1);
            *reinterpret_cast<__nv_bfloat162*>(&S.u.a.aggTl[t][d0]) = __nv_bfloat162(l0, l1);
            bsplit(a0, h0, l0); bsplit(a1, h1, l1);
            *reinterpret_cast<__nv_bfloat162*>(&S.u.a.aggTh[t][Dd + d0]) = __nv_bfloat162(h0, h1);
            *reinterpret_cast<__nv_bfloat162*>(&S.u.a.aggTl[t][Dd + d0]) = __nv_bfloat162(l0, l1);
            bsplit(b0, h0, l0); bsplit(b1, h1, l1);
            *reinterpret_cast<__nv_bfloat162*>(&S.u.a.aggTh[t][2 * Dd + d0]) = __nv_bfloat162(h0, h1);
            *reinterpret_cast<__nv_bfloat162*>(&S.u.a.aggTl[t][2 * Dd + d0]) = __nv_bfloat162(l0, l1);
        }
    }
    __syncthreads();

    // step 2: mma. warp w owns t-strip [16w, 16w+16); 8 n-tiles of 8 o's.
    const int w    = tid >> 5;
    const int lane = tid & 31;
    const int g    = lane >> 2;
    const int tg   = lane & 3;
    const int t0   = w * 16;

    float acc[8][4];
    #pragma unroll
    for (int j = 0; j < 8; ++j)
        #pragma unroll
        for (int q = 0; q < 4; ++q) acc[j][q] = 0.0f;

    #pragma unroll
    for (int ks = 0; ks < 6; ++ks) {
        const int ck = ks * 16;
        u32 ah[4], al[4];
        ah[0] = *reinterpret_cast<const u32*>(&S.u.a.aggTh[t0 + g    ][ck + 2 * tg]);
        ah[1] = *reinterpret_cast<const u32*>(&S.u.a.aggTh[t0 + 8 + g][ck + 2 * tg]);
        ah[2] = *reinterpret_cast<const u32*>(&S.u.a.aggTh[t0 + g    ][ck + 8 + 2 * tg]);
        ah[3] = *reinterpret_cast<const u32*>(&S.u.a.aggTh[t0 + 8 + g][ck + 8 + 2 * tg]);
        al[0] = *reinterpret_cast<const u32*>(&S.u.a.aggTl[t0 + g    ][ck + 2 * tg]);
        al[1] = *reinterpret_cast<const u32*>(&S.u.a.aggTl[t0 + 8 + g][ck + 2 * tg]);
        al[2] = *reinterpret_cast<const u32*>(&S.u.a.aggTl[t0 + g    ][ck + 8 + 2 * tg]);
        al[3] = *reinterpret_cast<const u32*>(&S.u.a.aggTl[t0 + 8 + g][ck + 8 + 2 * tg]);
        #pragma unroll
        for (int j = 0; j < 8; ++j) {
            const int n0 = j * 8 + g;
            u32 bh[2], bl[2];
            bh[0] = *reinterpret_cast<const u32*>(&S.Wh[n0][ck + 2 * tg]);
            bh[1] = *reinterpret_cast<const u32*>(&S.Wh[n0][ck + 8 + 2 * tg]);
            bl[0] = *reinterpret_cast<const u32*>(&S.Wl[n0][ck + 2 * tg]);
            bl[1] = *reinterpret_cast<const u32*>(&S.Wl[n0][ck + 8 + 2 * tg]);
            mma16816(acc[j], ah, bh);    // hi*hi
            mma16816(acc[j], ah, bl);    // hi*lo
            mma16816(acc[j], al, bh);    // lo*hi
        }
    }
    __syncthreads();   // all aggT reads done before ysm overwrites the union

    // relu + bias -> ysm  (banks (8tg+g) all distinct: conflict-free)
    #pragma unroll
    for (int j = 0; j < 8; ++j) {
        const int o0 = j * 8 + 2 * tg;
        const float2 bv = *reinterpret_cast<const float2*>(&bm[o0]);
        S.u.ysm[o0    ][t0 + g    ] = fmaxf(acc[j][0] + bv.x, 0.0f);
        S.u.ysm[o0 + 1][t0 + g    ] = fmaxf(acc[j][1] + bv.y, 0.0f);
        S.u.ysm[o0    ][t0 + 8 + g] = fmaxf(acc[j][2] + bv.x, 0.0f);
        S.u.ysm[o0 + 1][t0 + 8 + g] = fmaxf(acc[j][3] + bv.y, 0.0f);
    }
    __syncthreads();

    // final: t-coalesced global store. thread = (t, o-half)
    {
        const int t    = tid & 127;
        const int half = tid >> 7;
        float* ob = &out[(size_t)((b * Mm + m) * CO) * Tt + t];
        #pragma unroll 8
        for (int i = 0; i < CO / 2; ++i) {
            int o2 = half * (CO / 2) + i;
            ob[(size_t)o2 * Tt] = S.u.ysm[o2][t];
        }
    }
}

} // namespace

extern "C" void kernel_launch(void* const* d_in, const int* in_sizes, int n_in,
                              void* d_out, int out_size) {
    const float* fc   = (const float*)d_in[0];  // [2,512,32,128]
    const float* ft   = (const float*)d_in[1];  // [2,256,32,128]
    const float* adj  = (const float*)d_in[2];  // [2,2,256,512]
    const float* mask = (const float*)d_in[3];  // [2,128,512]
    const float* Wm   = (const float*)d_in[4];  // [64,96]
    const float* bm   = (const float*)d_in[5];  // [64]
    float* out = (float*)d_out;                 // [2,256,64,128]

    static bool init = false;
    if (!init) {
        cudaFuncSetAttribute(k_build_G, cudaFuncAttributeMaxDynamicSharedMemorySize, (int)sizeof(SB));
        cudaFuncSetAttribute(k_gemm,    cudaFuncAttributeMaxDynamicSharedMemorySize, (int)sizeof(SC));
        cudaFuncSetAttribute(k_epi,     cudaFuncAttributeMaxDynamicSharedMemorySize, (int)sizeof(SD));
        init = true;
    }

    k_split_adj<<<512, 256>>>(adj);
    k_build_G<<<dim3(Dd + 1, 8, Bb), 256, sizeof(SB)>>>(fc, mask);
    k_gemm<<<dim3(NC / 128, RR / 128, Bb), 256, sizeof(SC)>>>();
    k_epi<<<dim3(Mm, Bb), 256, sizeof(SD)>>>(ft, Wm, bm, out);
}